// round 6
// baseline (speedup 1.0000x reference)
#include <cuda_runtime.h>
#include <math.h>

#define F 128
#define NHEADS 8
#define SCALE 0.25f            // 1/sqrt(16)
#define MAXN 50048
#define MAXE 640064
#define OFFM (MAXN*NHEADS)
#define PGRID 304               // 2 CTAs x 152 SMs, persistent

// ---------------- device scratch (static: no allocations allowed) ----------
__device__ float g_q  [MAXN*F];          // q = node_h@Wq^T+bq
__device__ float g_v  [MAXN*F];          // v = node_h@Wv^T+bv
__device__ float g_Ein[MAXE*NHEADS];     // exp(scaled logits)
__device__ float g_Eou[MAXE*NHEADS];
__device__ float g_Edg[MAXE*NHEADS];
__device__ float g_att[MAXE];            // distance^lambda
__device__ float g_D  [3*OFFM];          // segment sums of exp
__device__ float g_Di [3*OFFM];          // 1/D
__device__ float g_S  [OFFM];            // per (node,head) score sum

// ---------------- helpers ---------------------------------------------------
__device__ __forceinline__ void ffma2(unsigned long long &c,
                                      unsigned long long a,
                                      unsigned long long b) {
    asm("fma.rn.f32x2 %0, %1, %2, %0;" : "+l"(c) : "l"(a), "l"(b));
}
__device__ __forceinline__ float pairsum(unsigned long long u) {
    float x, y;
    asm("mov.b64 {%0,%1}, %2;" : "=f"(x), "=f"(y) : "l"(u));
    return x + y;
}
__device__ __forceinline__ unsigned smem_u32(const void* p) {
    return (unsigned)__cvta_generic_to_shared(p);
}
__device__ __forceinline__ void cp16(unsigned d, const void* g) {
    asm volatile("cp.async.cg.shared.global [%0], [%1], 16;" :: "r"(d), "l"(g));
}
__device__ __forceinline__ void cp_wait() {
    asm volatile("cp.async.commit_group;\n\tcp.async.wait_group 0;" ::: "memory");
}

// shared layout (floats): sW[128*132] | sA[64*132] | sBias[128]
#define PW 132
#define SW_ELEMS (128*PW)
#define SA_ELEMS (64*PW)
#define SMEM_FLOATS (SW_ELEMS + SA_ELEMS + 128)

__device__ __forceinline__ void load_W(const float* __restrict__ W,
                                       const float* __restrict__ bias,
                                       float* sW, float* sB, int tid) {
#pragma unroll
    for (int j = 0; j < 16; j++) {
        int idx = j * 256 + tid;
        int r = idx >> 5, c4 = idx & 31;
        *(float4*)(sW + r * PW + c4 * 4) = *(const float4*)(W + r * 128 + c4 * 4);
    }
    if (tid < 128) sB[tid] = bias[tid];
}

// async-load one 64x128 A tile into sA (zero-padded past Mrows)
__device__ __forceinline__ void load_A_async(const float* __restrict__ A,
                                             float* sA, unsigned sA_b,
                                             int row0, int Mrows, int tid) {
#pragma unroll
    for (int j = 0; j < 8; j++) {
        int idx = j * 256 + tid; int r = idx >> 5, c4 = idx & 31;
        int gr = row0 + r;
        if (gr < Mrows) {
            cp16(sA_b + (unsigned)(r * PW + c4 * 4) * 4,
                 A + (size_t)gr * 128 + c4 * 4);
        } else {
            *(float4*)(sA + r * PW + c4 * 4) = make_float4(0.f, 0.f, 0.f, 0.f);
        }
    }
    cp_wait();
}

// core 64x128x128 tile GEMM with f32x2 packed FMAs.
// thread tile: 8 rows x 4 cols (cols tc, tc+32, tc+64, tc+96)
__device__ __forceinline__ void gemm_compute(const float* sA, const float* sW,
                                             int tid, unsigned long long (&acc)[8][4]) {
    int tc = tid & 31, trg = tid >> 5;
#pragma unroll
    for (int r = 0; r < 8; r++)
#pragma unroll
        for (int c = 0; c < 4; c++) acc[r][c] = 0ull;
    const float* aB = sA + trg * 8 * PW;
#pragma unroll 4
    for (int i = 0; i < 128; i += 4) {
        ulonglong2 a2[8], b2[4];
#pragma unroll
        for (int r = 0; r < 8; r++)
            a2[r] = *(const ulonglong2*)(aB + r * PW + i);      // broadcast
#pragma unroll
        for (int c = 0; c < 4; c++)
            b2[c] = *(const ulonglong2*)(sW + (tc + 32 * c) * PW + i);  // conflict-free
#pragma unroll
        for (int r = 0; r < 8; r++)
#pragma unroll
            for (int c = 0; c < 4; c++) {
                ffma2(acc[r][c], a2[r].x, b2[c].x);
                ffma2(acc[r][c], a2[r].y, b2[c].y);
            }
    }
}

// ---------------- kernels ---------------------------------------------------

// persistent q / v projection: C = A @ W^T + b
__global__ void __launch_bounds__(256) gemm_qv_kernel(const float* __restrict__ A,
                                                      const float* __restrict__ W,
                                                      const float* __restrict__ bias,
                                                      int Mrows, int which) {
    extern __shared__ float sm[];
    float* sW = sm; float* sA = sm + SW_ELEMS; float* sB = sA + SA_ELEMS;
    int tid = threadIdx.x;
    unsigned sA_b = smem_u32(sA);
    load_W(W, bias, sW, sB, tid);
    float* C = which ? g_v : g_q;
    int ntiles = (Mrows + 63) >> 6;
    int tc = tid & 31, trg = tid >> 5;
    for (int tile = blockIdx.x; tile < ntiles; tile += gridDim.x) {
        int row0 = tile * 64;
        load_A_async(A, sA, sA_b, row0, Mrows, tid);
        __syncthreads();
        unsigned long long acc[8][4];
        gemm_compute(sA, sW, tid, acc);
#pragma unroll
        for (int r = 0; r < 8; r++) {
            int gr = row0 + trg * 8 + r;
            if (gr < Mrows) {
#pragma unroll
                for (int c = 0; c < 4; c++) {
                    int col = tc + 32 * c;
                    C[(size_t)gr * 128 + col] = pairsum(acc[r][c]) + sB[col];
                }
            }
        }
        __syncthreads();   // sA reads done before next tile's cp.async
    }
}

// persistent fused: k = edge_h@Wk^T+bk (smem only) -> logits -> exp -> denom atomics
__global__ void __launch_bounds__(256) k_logits_kernel(const float* __restrict__ edge_h,
                                                       const float* __restrict__ Wk,
                                                       const float* __restrict__ bk,
                                                       const int* __restrict__ src,
                                                       const int* __restrict__ dst,
                                                       int E) {
    extern __shared__ float sm[];
    float* sW = sm; float* sA = sm + SW_ELEMS; float* sB = sA + SA_ELEMS;
    int tid = threadIdx.x;
    unsigned sA_b = smem_u32(sA);
    load_W(Wk, bk, sW, sB, tid);
    int ntiles = (E + 63) >> 6;
    int tc = tid & 31, trg = tid >> 5;
    for (int tile = blockIdx.x; tile < ntiles; tile += gridDim.x) {
        int row0 = tile * 64;
        load_A_async(edge_h, sA, sA_b, row0, E, tid);
        __syncthreads();
        unsigned long long acc[8][4];
        gemm_compute(sA, sW, tid, acc);
        __syncthreads();                       // all reads of sA done
        // write k tile back into sA
#pragma unroll
        for (int r = 0; r < 8; r++)
#pragma unroll
            for (int c = 0; c < 4; c++) {
                int col = tc + 32 * c;
                sA[(trg * 8 + r) * PW + col] = pairsum(acc[r][c]) + sB[col];
            }
        __syncthreads();
        // logits + exp + denominator atomics: one item per (edge-in-tile, head)
#pragma unroll
        for (int w = tid; w < 64 * NHEADS; w += 256) {
            int et = w >> 3, h = w & 7;
            int e = row0 + et;
            if (e < E) {
                int s = src[e], d = dst[e];
                const float4* qs = (const float4*)(g_q + (size_t)s * 128 + h * 16);
                const float4* qd = (const float4*)(g_q + (size_t)d * 128 + h * 16);
                const float4* kk = (const float4*)(sA + et * PW + h * 16);
                float im = 0.f, om = 0.f, dg = 0.f;
#pragma unroll
                for (int j = 0; j < 4; j++) {
                    float4 a = qs[j], b = qd[j], c = kk[j];
                    im += a.x * c.x + a.y * c.y + a.z * c.z + a.w * c.w;
                    om += b.x * c.x + b.y * c.y + b.z * c.z + b.w * c.w;
                    dg += a.x * b.x + a.y * b.y + a.z * b.z + a.w * b.w;
                }
                float ein = expf(im * SCALE);
                float eou = expf(om * SCALE);
                float edg = expf(dg * SCALE);
                size_t o = (size_t)e * NHEADS + h;
                g_Ein[o] = ein;  g_Eou[o] = eou;  g_Edg[o] = edg;
                int idx = d * NHEADS + h;
                atomicAdd(&g_D[idx],            ein);
                atomicAdd(&g_D[OFFM + idx],     eou);
                atomicAdd(&g_D[2 * OFFM + idx], edg);
            }
        }
        __syncthreads();   // sA epilogue reads done before next cp.async
    }
}

__global__ void init_kernel(const float* __restrict__ dist,
                            const float* __restrict__ lam, int E) {
    int t = blockIdx.x * blockDim.x + threadIdx.x;
    if (t < 3 * OFFM) g_D[t] = 0.f;
    if (t < OFFM) g_S[t] = 0.f;
    if (t < E) g_att[t] = powf(dist[t], lam[0]);
}

__global__ void recip_kernel(int N) {
    int t = blockIdx.x * blockDim.x + threadIdx.x;
    if (t >= N * NHEADS) return;
#pragma unroll
    for (int k = 0; k < 3; k++) {
        float d = g_D[k * OFFM + t];
        g_Di[k * OFFM + t] = (d != 0.f) ? 1.f / d : 0.f;
    }
}

__global__ void score_kernel(const int* __restrict__ dst, int E) {
    int t = blockIdx.x * blockDim.x + threadIdx.x;
    if (t >= E * NHEADS) return;
    int e = t >> 3, h = t & 7;
    int idx = dst[e] * NHEADS + h;
    float s = g_Ein[t] * g_Di[idx]
            + g_Eou[t] * g_Di[OFFM + idx]
            + g_Edg[t] * g_Di[2 * OFFM + idx];
    atomicAdd(&g_S[idx], s * g_att[e]);
}

// persistent: out = leaky_relu( (S ⊙ v) @ Wo^T + bo )
__global__ void __launch_bounds__(256) out_kernel(const float* __restrict__ Wo,
                                                  const float* __restrict__ bo,
                                                  float* __restrict__ out, int N) {
    extern __shared__ float sm[];
    float* sW = sm; float* sA = sm + SW_ELEMS; float* sB = sA + SA_ELEMS;
    int tid = threadIdx.x;
    load_W(Wo, bo, sW, sB, tid);
    int ntiles = (N + 63) >> 6;
    int tc = tid & 31, trg = tid >> 5;
    for (int tile = blockIdx.x; tile < ntiles; tile += gridDim.x) {
        int row0 = tile * 64;
        __syncthreads();   // prior tile's sA reads done (also covers first-iter W)
#pragma unroll
        for (int j = 0; j < 8; j++) {
            int idx = j * 256 + tid; int r = idx >> 5, c4 = idx & 31;
            int gr = row0 + r;
            float4 a = make_float4(0.f, 0.f, 0.f, 0.f);
            if (gr < N) {
                a = *(const float4*)(g_v + (size_t)gr * 128 + c4 * 4);
                float sc = g_S[gr * NHEADS + (c4 >> 2)];   // head = (c4*4)/16
                a.x *= sc; a.y *= sc; a.z *= sc; a.w *= sc;
            }
            *(float4*)(sA + r * PW + c4 * 4) = a;
        }
        __syncthreads();
        unsigned long long acc[8][4];
        gemm_compute(sA, sW, tid, acc);
#pragma unroll
        for (int r = 0; r < 8; r++) {
            int gr = row0 + trg * 8 + r;
            if (gr < N) {
#pragma unroll
                for (int c = 0; c < 4; c++) {
                    int col = tc + 32 * c;
                    float x = pairsum(acc[r][c]) + sB[col];
                    out[(size_t)gr * 128 + col] = (x > 0.f) ? x : 0.1f * x;
                }
            }
        }
    }
}

// ---------------- launch -----------------------------------------------------
extern "C" void kernel_launch(void* const* d_in, const int* in_sizes, int n_in,
                              void* d_out, int out_size) {
    const float* node_h   = (const float*)d_in[0];
    const float* edge_h   = (const float*)d_in[1];
    const float* distance = (const float*)d_in[2];
    const float* Wq = (const float*)d_in[3];  const float* bq = (const float*)d_in[4];
    const float* Wk = (const float*)d_in[5];  const float* bk = (const float*)d_in[6];
    const float* Wv = (const float*)d_in[7];  const float* bv = (const float*)d_in[8];
    const float* Wo = (const float*)d_in[9];  const float* bo = (const float*)d_in[10];
    const float* lam = (const float*)d_in[11];
    const int*   src = (const int*)d_in[12];
    const int*   dst = (const int*)d_in[13];

    int N = in_sizes[0] / F;
    int E = in_sizes[12];
    float* out = (float*)d_out;

    size_t smemB = SMEM_FLOATS * sizeof(float);   // ~99.5 KB -> 2 CTAs/SM
    cudaFuncSetAttribute(gemm_qv_kernel, cudaFuncAttributeMaxDynamicSharedMemorySize, (int)smemB);
    cudaFuncSetAttribute(k_logits_kernel, cudaFuncAttributeMaxDynamicSharedMemorySize, (int)smemB);
    cudaFuncSetAttribute(out_kernel, cudaFuncAttributeMaxDynamicSharedMemorySize, (int)smemB);

    int ib = (3 * OFFM + 255) / 256;
    init_kernel<<<ib, 256>>>(distance, lam, E);

    gemm_qv_kernel<<<PGRID, 256, smemB>>>(node_h, Wq, bq, N, 0);
    gemm_qv_kernel<<<PGRID, 256, smemB>>>(node_h, Wv, bv, N, 1);

    k_logits_kernel<<<PGRID, 256, smemB>>>(edge_h, Wk, bk, src, dst, E);

    int tb = (E * NHEADS + 255) / 256;
    int db = (N * NHEADS + 255) / 256;
    recip_kernel<<<db, 256>>>(N);
    score_kernel<<<tb, 256>>>(dst, E);

    out_kernel<<<PGRID, 256, smemB>>>(Wo, bo, out, N);
}

// round 7
// speedup vs baseline: 1.0164x; 1.0164x over previous
#include <cuda_runtime.h>
#include <math.h>

#define F 128
#define NHEADS 8
#define SCALE 0.25f            // 1/sqrt(16)
#define MAXN 50048
#define MAXE 640064
#define OFFM (MAXN*NHEADS)
#define PGRID 304               // 2 CTAs x 152 SMs, persistent

// ---------------- device scratch (static: no allocations allowed) ----------
__device__ float g_q  [MAXN*F];          // q = node_h@Wq^T+bq
__device__ float g_v  [MAXN*F];          // v = node_h@Wv^T+bv
__device__ float g_Ein[MAXE*NHEADS];     // exp(scaled logits)
__device__ float g_Eou[MAXE*NHEADS];
__device__ float g_Edg[MAXE*NHEADS];
__device__ float g_att[MAXE];            // distance^lambda
__device__ float g_D  [3*OFFM];          // segment sums of exp
__device__ float g_Di [3*OFFM];          // 1/D
__device__ float g_S  [OFFM];            // per (node,head) score sum

// ---------------- helpers ---------------------------------------------------
__device__ __forceinline__ void ffma2(unsigned long long &c,
                                      unsigned long long a,
                                      unsigned long long b) {
    asm("fma.rn.f32x2 %0, %1, %2, %0;" : "+l"(c) : "l"(a), "l"(b));
}
__device__ __forceinline__ float pairsum(unsigned long long u) {
    float x, y;
    asm("mov.b64 {%0,%1}, %2;" : "=f"(x), "=f"(y) : "l"(u));
    return x + y;
}

// shared layout (floats): sW[128*132] | sA[64*132] | sBias[128]
#define PW 132
#define SW_ELEMS (128*PW)
#define SA_ELEMS (64*PW)
#define SMEM_FLOATS (SW_ELEMS + SA_ELEMS + 128)

__device__ __forceinline__ void load_W(const float* __restrict__ W,
                                       const float* __restrict__ bias,
                                       float* sW, float* sB, int tid) {
#pragma unroll
    for (int j = 0; j < 16; j++) {
        int idx = j * 256 + tid;
        int r = idx >> 5, c4 = idx & 31;
        *(float4*)(sW + r * PW + c4 * 4) = *(const float4*)(W + r * 128 + c4 * 4);
    }
    if (tid < 128) sB[tid] = bias[tid];
}

// synchronous A-tile load (zero-padded past Mrows); plain LDG.128 -> STS
__device__ __forceinline__ void load_A(const float* __restrict__ A,
                                       float* sA, int row0, int Mrows, int tid) {
#pragma unroll
    for (int j = 0; j < 8; j++) {
        int idx = j * 256 + tid; int r = idx >> 5, c4 = idx & 31;
        int gr = row0 + r;
        float4 a = make_float4(0.f, 0.f, 0.f, 0.f);
        if (gr < Mrows) a = *(const float4*)(A + (size_t)gr * 128 + c4 * 4);
        *(float4*)(sA + r * PW + c4 * 4) = a;
    }
}

// core 64x128x128 tile GEMM with f32x2 packed FMAs.
// thread tile: 8 rows x 4 cols (cols tc, tc+32, tc+64, tc+96)
__device__ __forceinline__ void gemm_compute(const float* sA, const float* sW,
                                             int tid, unsigned long long (&acc)[8][4]) {
    int tc = tid & 31, trg = tid >> 5;
#pragma unroll
    for (int r = 0; r < 8; r++)
#pragma unroll
        for (int c = 0; c < 4; c++) acc[r][c] = 0ull;
    const float* aB = sA + trg * 8 * PW;
#pragma unroll 4
    for (int i = 0; i < 128; i += 4) {
        ulonglong2 a2[8], b2[4];
#pragma unroll
        for (int r = 0; r < 8; r++)
            a2[r] = *(const ulonglong2*)(aB + r * PW + i);      // broadcast
#pragma unroll
        for (int c = 0; c < 4; c++)
            b2[c] = *(const ulonglong2*)(sW + (tc + 32 * c) * PW + i);  // conflict-free
#pragma unroll
        for (int r = 0; r < 8; r++)
#pragma unroll
            for (int c = 0; c < 4; c++) {
                ffma2(acc[r][c], a2[r].x, b2[c].x);
                ffma2(acc[r][c], a2[r].y, b2[c].y);
            }
    }
}

// ---------------- kernels ---------------------------------------------------

// persistent q / v projection: C = A @ W^T + b
__global__ void __launch_bounds__(256, 2) gemm_qv_kernel(const float* __restrict__ A,
                                                         const float* __restrict__ W,
                                                         const float* __restrict__ bias,
                                                         int Mrows, int which) {
    extern __shared__ float sm[];
    float* sW = sm; float* sA = sm + SW_ELEMS; float* sB = sA + SA_ELEMS;
    int tid = threadIdx.x;
    load_W(W, bias, sW, sB, tid);
    float* C = which ? g_v : g_q;
    int ntiles = (Mrows + 63) >> 6;
    int tc = tid & 31, trg = tid >> 5;
    for (int tile = blockIdx.x; tile < ntiles; tile += gridDim.x) {
        int row0 = tile * 64;
        load_A(A, sA, row0, Mrows, tid);
        __syncthreads();
        unsigned long long acc[8][4];
        gemm_compute(sA, sW, tid, acc);
#pragma unroll
        for (int r = 0; r < 8; r++) {
            int gr = row0 + trg * 8 + r;
            if (gr < Mrows) {
#pragma unroll
                for (int c = 0; c < 4; c++) {
                    int col = tc + 32 * c;
                    C[(size_t)gr * 128 + col] = pairsum(acc[r][c]) + sB[col];
                }
            }
        }
        __syncthreads();   // sA reads done before next tile's stores
    }
}

// persistent fused: k = edge_h@Wk^T+bk (smem only) -> logits -> exp -> denom atomics
__global__ void __launch_bounds__(256, 2) k_logits_kernel(const float* __restrict__ edge_h,
                                                          const float* __restrict__ Wk,
                                                          const float* __restrict__ bk,
                                                          const int* __restrict__ src,
                                                          const int* __restrict__ dst,
                                                          int E) {
    extern __shared__ float sm[];
    float* sW = sm; float* sA = sm + SW_ELEMS; float* sB = sA + SA_ELEMS;
    int tid = threadIdx.x;
    load_W(Wk, bk, sW, sB, tid);
    int ntiles = (E + 63) >> 6;
    int tc = tid & 31, trg = tid >> 5;
    int et0 = tid >> 3;          // edge-in-tile for item 0 (0..31)
    int h   = tid & 7;           // head
    for (int tile = blockIdx.x; tile < ntiles; tile += gridDim.x) {
        int row0 = tile * 64;
        load_A(edge_h, sA, row0, E, tid);

        // preload this thread's epilogue indices NOW; consumed after the GEMM,
        // so the load latency hides under ~8k cycles of FFMA2.
        int e0 = row0 + et0, e1 = e0 + 32;
        bool v0 = e0 < E, v1 = e1 < E;
        int s0 = 0, d0 = 0, s1 = 0, d1 = 0;
        if (v0) { s0 = __ldg(src + e0); d0 = __ldg(dst + e0); }
        if (v1) { s1 = __ldg(src + e1); d1 = __ldg(dst + e1); }

        __syncthreads();
        {
            unsigned long long acc[8][4];
            gemm_compute(sA, sW, tid, acc);
            __syncthreads();                       // all reads of sA done
            // write k tile back into sA
#pragma unroll
            for (int r = 0; r < 8; r++)
#pragma unroll
                for (int c = 0; c < 4; c++) {
                    int col = tc + 32 * c;
                    sA[(trg * 8 + r) * PW + col] = pairsum(acc[r][c]) + sB[col];
                }
        }
        __syncthreads();

        // ---- epilogue: batched gathers (MLP 16), logits, exp, denom atomics
        {
            float4 qs0[4], qd0[4], qs1[4], qd1[4];
            const float4* p_qs0 = (const float4*)(g_q + (size_t)s0 * 128 + h * 16);
            const float4* p_qd0 = (const float4*)(g_q + (size_t)d0 * 128 + h * 16);
            const float4* p_qs1 = (const float4*)(g_q + (size_t)s1 * 128 + h * 16);
            const float4* p_qd1 = (const float4*)(g_q + (size_t)d1 * 128 + h * 16);
            if (v0) {
#pragma unroll
                for (int j = 0; j < 4; j++) { qs0[j] = p_qs0[j]; qd0[j] = p_qd0[j]; }
            }
            if (v1) {
#pragma unroll
                for (int j = 0; j < 4; j++) { qs1[j] = p_qs1[j]; qd1[j] = p_qd1[j]; }
            }
            if (v0) {
                const float4* kk = (const float4*)(sA + et0 * PW + h * 16);
                float im = 0.f, om = 0.f, dg = 0.f;
#pragma unroll
                for (int j = 0; j < 4; j++) {
                    float4 a = qs0[j], b = qd0[j], c = kk[j];
                    im += a.x * c.x + a.y * c.y + a.z * c.z + a.w * c.w;
                    om += b.x * c.x + b.y * c.y + b.z * c.z + b.w * c.w;
                    dg += a.x * b.x + a.y * b.y + a.z * b.z + a.w * b.w;
                }
                float ein = __expf(im * SCALE);
                float eou = __expf(om * SCALE);
                float edg = __expf(dg * SCALE);
                size_t o = (size_t)e0 * NHEADS + h;
                g_Ein[o] = ein; g_Eou[o] = eou; g_Edg[o] = edg;
                int idx = d0 * NHEADS + h;
                atomicAdd(&g_D[idx],            ein);
                atomicAdd(&g_D[OFFM + idx],     eou);
                atomicAdd(&g_D[2 * OFFM + idx], edg);
            }
            if (v1) {
                const float4* kk = (const float4*)(sA + (et0 + 32) * PW + h * 16);
                float im = 0.f, om = 0.f, dg = 0.f;
#pragma unroll
                for (int j = 0; j < 4; j++) {
                    float4 a = qs1[j], b = qd1[j], c = kk[j];
                    im += a.x * c.x + a.y * c.y + a.z * c.z + a.w * c.w;
                    om += b.x * c.x + b.y * c.y + b.z * c.z + b.w * c.w;
                    dg += a.x * b.x + a.y * b.y + a.z * b.z + a.w * b.w;
                }
                float ein = __expf(im * SCALE);
                float eou = __expf(om * SCALE);
                float edg = __expf(dg * SCALE);
                size_t o = (size_t)e1 * NHEADS + h;
                g_Ein[o] = ein; g_Eou[o] = eou; g_Edg[o] = edg;
                int idx = d1 * NHEADS + h;
                atomicAdd(&g_D[idx],            ein);
                atomicAdd(&g_D[OFFM + idx],     eou);
                atomicAdd(&g_D[2 * OFFM + idx], edg);
            }
        }
        __syncthreads();   // sA epilogue reads done before next tile's stores
    }
}

__global__ void init_kernel(const float* __restrict__ dist,
                            const float* __restrict__ lam, int E) {
    int t = blockIdx.x * blockDim.x + threadIdx.x;
    if (t < 3 * OFFM) g_D[t] = 0.f;
    if (t < OFFM) g_S[t] = 0.f;
    if (t < E) g_att[t] = powf(dist[t], lam[0]);
}

__global__ void recip_kernel(int N) {
    int t = blockIdx.x * blockDim.x + threadIdx.x;
    if (t >= N * NHEADS) return;
#pragma unroll
    for (int k = 0; k < 3; k++) {
        float d = g_D[k * OFFM + t];
        g_Di[k * OFFM + t] = (d != 0.f) ? 1.f / d : 0.f;
    }
}

__global__ void score_kernel(const int* __restrict__ dst, int E) {
    int t = blockIdx.x * blockDim.x + threadIdx.x;
    if (t >= E * NHEADS) return;
    int e = t >> 3, h = t & 7;
    int idx = dst[e] * NHEADS + h;
    float s = g_Ein[t] * g_Di[idx]
            + g_Eou[t] * g_Di[OFFM + idx]
            + g_Edg[t] * g_Di[2 * OFFM + idx];
    atomicAdd(&g_S[idx], s * g_att[e]);
}

// persistent: out = leaky_relu( (S ⊙ v) @ Wo^T + bo )
__global__ void __launch_bounds__(256, 2) out_kernel(const float* __restrict__ Wo,
                                                     const float* __restrict__ bo,
                                                     float* __restrict__ out, int N) {
    extern __shared__ float sm[];
    float* sW = sm; float* sA = sm + SW_ELEMS; float* sB = sA + SA_ELEMS;
    int tid = threadIdx.x;
    load_W(Wo, bo, sW, sB, tid);
    int ntiles = (N + 63) >> 6;
    int tc = tid & 31, trg = tid >> 5;
    for (int tile = blockIdx.x; tile < ntiles; tile += gridDim.x) {
        int row0 = tile * 64;
        __syncthreads();   // prior tile's sA reads done (also covers first-iter W)
#pragma unroll
        for (int j = 0; j < 8; j++) {
            int idx = j * 256 + tid; int r = idx >> 5, c4 = idx & 31;
            int gr = row0 + r;
            float4 a = make_float4(0.f, 0.f, 0.f, 0.f);
            if (gr < N) {
                a = *(const float4*)(g_v + (size_t)gr * 128 + c4 * 4);
                float sc = g_S[gr * NHEADS + (c4 >> 2)];   // head = (c4*4)/16
                a.x *= sc; a.y *= sc; a.z *= sc; a.w *= sc;
            }
            *(float4*)(sA + r * PW + c4 * 4) = a;
        }
        __syncthreads();
        unsigned long long acc[8][4];
        gemm_compute(sA, sW, tid, acc);
#pragma unroll
        for (int r = 0; r < 8; r++) {
            int gr = row0 + trg * 8 + r;
            if (gr < N) {
#pragma unroll
                for (int c = 0; c < 4; c++) {
                    int col = tc + 32 * c;
                    float x = pairsum(acc[r][c]) + sB[col];
                    out[(size_t)gr * 128 + col] = (x > 0.f) ? x : 0.1f * x;
                }
            }
        }
    }
}

// ---------------- launch -----------------------------------------------------
extern "C" void kernel_launch(void* const* d_in, const int* in_sizes, int n_in,
                              void* d_out, int out_size) {
    const float* node_h   = (const float*)d_in[0];
    const float* edge_h   = (const float*)d_in[1];
    const float* distance = (const float*)d_in[2];
    const float* Wq = (const float*)d_in[3];  const float* bq = (const float*)d_in[4];
    const float* Wk = (const float*)d_in[5];  const float* bk = (const float*)d_in[6];
    const float* Wv = (const float*)d_in[7];  const float* bv = (const float*)d_in[8];
    const float* Wo = (const float*)d_in[9];  const float* bo = (const float*)d_in[10];
    const float* lam = (const float*)d_in[11];
    const int*   src = (const int*)d_in[12];
    const int*   dst = (const int*)d_in[13];

    int N = in_sizes[0] / F;
    int E = in_sizes[12];
    float* out = (float*)d_out;

    size_t smemB = SMEM_FLOATS * sizeof(float);   // ~99.5 KB -> 2 CTAs/SM
    cudaFuncSetAttribute(gemm_qv_kernel, cudaFuncAttributeMaxDynamicSharedMemorySize, (int)smemB);
    cudaFuncSetAttribute(k_logits_kernel, cudaFuncAttributeMaxDynamicSharedMemorySize, (int)smemB);
    cudaFuncSetAttribute(out_kernel, cudaFuncAttributeMaxDynamicSharedMemorySize, (int)smemB);

    int ib = (3 * OFFM + 255) / 256;
    init_kernel<<<ib, 256>>>(distance, lam, E);

    gemm_qv_kernel<<<PGRID, 256, smemB>>>(node_h, Wq, bq, N, 0);
    gemm_qv_kernel<<<PGRID, 256, smemB>>>(node_h, Wv, bv, N, 1);

    k_logits_kernel<<<PGRID, 256, smemB>>>(edge_h, Wk, bk, src, dst, E);

    int tb = (E * NHEADS + 255) / 256;
    int db = (N * NHEADS + 255) / 256;
    recip_kernel<<<db, 256>>>(N);
    score_kernel<<<tb, 256>>>(dst, E);

    out_kernel<<<PGRID, 256, smemB>>>(Wo, bo, out, N);
}

// round 9
// speedup vs baseline: 1.7667x; 1.7382x over previous
#include <cuda_runtime.h>
#include <cuda_bf16.h>
#include <math.h>

#define F 128
#define NHEADS 8
#define SCALE 0.25f            // 1/sqrt(16)
#define MAXN 50048
#define MAXE 640064
#define OFFM (MAXN*NHEADS)
#define PGRID 152               // persistent, 1 CTA/SM

// ---------------- device scratch (static: no allocations allowed) ----------
__device__ float g_q  [MAXN*F];
__device__ float g_v  [MAXN*F];
__device__ float g_Ein[MAXE*NHEADS];
__device__ float g_Eou[MAXE*NHEADS];
__device__ float g_Edg[MAXE*NHEADS];
__device__ float g_att[MAXE];
__device__ float g_D  [3*OFFM];
__device__ float g_Di [3*OFFM];
__device__ float g_S  [OFFM];

// ---------------- helpers ---------------------------------------------------
// pack two floats to bf16x2 (first arg -> low half)
__device__ __forceinline__ unsigned pack_bf2(float flo, float fhi) {
    unsigned r;
    asm("cvt.rn.satfinite.bf16x2.f32 %0, %1, %2;" : "=r"(r) : "f"(fhi), "f"(flo));
    return r;
}

// warp mma: C[16x8] += A[16x16](bf16,row) * B[16x8](bf16,col), fp32 acc
__device__ __forceinline__ void mma_bf16(float (&c)[4], const unsigned (&a)[4],
                                         const unsigned (&b)[2]) {
    asm volatile("mma.sync.aligned.m16n8k16.row.col.f32.bf16.bf16.f32 "
        "{%0,%1,%2,%3}, {%4,%5,%6,%7}, {%8,%9}, {%0,%1,%2,%3};"
        : "+f"(c[0]), "+f"(c[1]), "+f"(c[2]), "+f"(c[3])
        : "r"(a[0]), "r"(a[1]), "r"(a[2]), "r"(a[3]), "r"(b[0]), "r"(b[1]));
}

// bf16 tile row stride (elements): 128 data + 8 pad -> conflict-free fragments
#define SAW 136
#define TB  (128*SAW*2)          // bytes per 128x128 bf16 tile (34816)
#define KPW 132                  // fp32 k-tile row stride (floats)

// convert a 128x128 fp32 block (rows row0.., zero-padded past nrows) into
// hi/lo bf16 split tiles in smem. scl: optional per-(row,head) scale.
template<int NT, bool SCALED>
__device__ __forceinline__ void load_conv(const float* __restrict__ src, int row0, int nrows,
                                          __nv_bfloat16* aHi, __nv_bfloat16* aLo,
                                          int tid, const float* __restrict__ scl) {
    for (int g = tid; g < 2048; g += NT) {
        int row = g >> 4, c8 = (g & 15) << 3;
        float fs[8] = {0.f, 0.f, 0.f, 0.f, 0.f, 0.f, 0.f, 0.f};
        int gr = row0 + row;
        if (gr < nrows) {
            const float4* p = (const float4*)(src + (size_t)gr * 128 + c8);
            float4 f0 = p[0], f1 = p[1];
            fs[0] = f0.x; fs[1] = f0.y; fs[2] = f0.z; fs[3] = f0.w;
            fs[4] = f1.x; fs[5] = f1.y; fs[6] = f1.z; fs[7] = f1.w;
            if (SCALED) {
                float sc = scl[gr * NHEADS + (c8 >> 4)];
#pragma unroll
                for (int j = 0; j < 8; j++) fs[j] *= sc;
            }
        }
        unsigned hi[4], lo[4];
#pragma unroll
        for (int j = 0; j < 4; j++) {
            unsigned h = pack_bf2(fs[2 * j], fs[2 * j + 1]);
            float h0f = __uint_as_float(h << 16);
            float h1f = __uint_as_float(h & 0xFFFF0000u);
            hi[j] = h;
            lo[j] = pack_bf2(fs[2 * j] - h0f, fs[2 * j + 1] - h1f);
        }
        *(uint4*)(aHi + row * SAW + c8) = make_uint4(hi[0], hi[1], hi[2], hi[3]);
        *(uint4*)(aLo + row * SAW + c8) = make_uint4(lo[0], lo[1], lo[2], lo[3]);
    }
}

// one warp's 16x64 share of C = A[128x128] @ W^T[128x128] with bf16 split.
// wr: warp row base (0..112), wc: warp col base (0 or 64).
__device__ __forceinline__ void mma_tile(const __nv_bfloat16* aH, const __nv_bfloat16* aL,
                                         const __nv_bfloat16* wH, const __nv_bfloat16* wL,
                                         int lane, int wr, int wc, float (&acc)[8][4]) {
    int qp = (lane & 3) * 2;
    int r0 = wr + (lane >> 2);
#pragma unroll
    for (int nt = 0; nt < 8; nt++)
#pragma unroll
        for (int c = 0; c < 4; c++) acc[nt][c] = 0.f;
#pragma unroll
    for (int ks = 0; ks < 8; ks++) {
        int kc = ks * 16 + qp;
        unsigned aHf[4], aLf[4];
        aHf[0] = *(const unsigned*)(aH + r0 * SAW + kc);
        aHf[1] = *(const unsigned*)(aH + (r0 + 8) * SAW + kc);
        aHf[2] = *(const unsigned*)(aH + r0 * SAW + kc + 8);
        aHf[3] = *(const unsigned*)(aH + (r0 + 8) * SAW + kc + 8);
        aLf[0] = *(const unsigned*)(aL + r0 * SAW + kc);
        aLf[1] = *(const unsigned*)(aL + (r0 + 8) * SAW + kc);
        aLf[2] = *(const unsigned*)(aL + r0 * SAW + kc + 8);
        aLf[3] = *(const unsigned*)(aL + (r0 + 8) * SAW + kc + 8);
#pragma unroll
        for (int nt = 0; nt < 8; nt++) {
            int n = wc + nt * 8 + (lane >> 2);
            unsigned bHf[2], bLf[2];
            bHf[0] = *(const unsigned*)(wH + n * SAW + kc);
            bHf[1] = *(const unsigned*)(wH + n * SAW + kc + 8);
            bLf[0] = *(const unsigned*)(wL + n * SAW + kc);
            bLf[1] = *(const unsigned*)(wL + n * SAW + kc + 8);
            mma_bf16(acc[nt], aHf, bHf);
            mma_bf16(acc[nt], aHf, bLf);
            mma_bf16(acc[nt], aLf, bHf);
        }
    }
}

// ---------------- smem layouts (byte offsets) -------------------------------
// k_logits: WH|WL|AH|AL|kf32|bias
#define K_WH 0
#define K_WL TB
#define K_AH (2*TB)
#define K_AL (3*TB)
#define K_KF (4*TB)
#define K_SB (K_KF + 128*KPW*4)
#define K_SMEM (K_SB + 512)
// qv: WqH|WqL|WvH|WvL|AH|AL|biases
#define QV_WQH 0
#define QV_WQL TB
#define QV_WVH (2*TB)
#define QV_WVL (3*TB)
#define QV_AH  (4*TB)
#define QV_AL  (5*TB)
#define QV_SBQ (6*TB)
#define QV_SBV (QV_SBQ + 512)
#define QV_SMEM (QV_SBV + 512)
// out: WH|WL|AH|AL|bias
#define O_WH 0
#define O_WL TB
#define O_AH (2*TB)
#define O_AL (3*TB)
#define O_SB (4*TB)
#define O_SMEM (O_SB + 512)

// ---------------- kernels ---------------------------------------------------

// persistent q+v projection via HMMA
__global__ void __launch_bounds__(512, 1) qv_tc_kernel(const float* __restrict__ node_h,
        const float* __restrict__ Wq, const float* __restrict__ bq,
        const float* __restrict__ Wv, const float* __restrict__ bv, int N) {
    extern __shared__ char sm[];
    int tid = threadIdx.x, wid = tid >> 5, lane = tid & 31;
    __nv_bfloat16* WqH = (__nv_bfloat16*)(sm + QV_WQH);
    __nv_bfloat16* WqL = (__nv_bfloat16*)(sm + QV_WQL);
    __nv_bfloat16* WvH = (__nv_bfloat16*)(sm + QV_WVH);
    __nv_bfloat16* WvL = (__nv_bfloat16*)(sm + QV_WVL);
    __nv_bfloat16* AH  = (__nv_bfloat16*)(sm + QV_AH);
    __nv_bfloat16* AL  = (__nv_bfloat16*)(sm + QV_AL);
    float* sBq = (float*)(sm + QV_SBQ);
    float* sBv = (float*)(sm + QV_SBV);
    load_conv<512, false>(Wq, 0, 128, WqH, WqL, tid, nullptr);
    load_conv<512, false>(Wv, 0, 128, WvH, WvL, tid, nullptr);
    if (tid < 128) { sBq[tid] = bq[tid]; sBv[tid] = bv[tid]; }
    __syncthreads();
    int wr = (wid >> 1) << 4, wc = (wid & 1) << 6;
    int qp = (lane & 3) * 2;
    int ntiles = (N + 127) >> 7;
    for (int tile = blockIdx.x; tile < ntiles; tile += gridDim.x) {
        int row0 = tile << 7;
        load_conv<512, false>(node_h, row0, N, AH, AL, tid, nullptr);
        __syncthreads();
        float acc[8][4];
        // ---- q ----
        mma_tile(AH, AL, WqH, WqL, lane, wr, wc, acc);
        {
            int r = wr + (lane >> 2);
            int gr0 = row0 + r, gr1 = gr0 + 8;
#pragma unroll
            for (int nt = 0; nt < 8; nt++) {
                int col = wc + nt * 8 + qp;
                if (gr0 < N) *(float2*)(g_q + (size_t)gr0 * 128 + col) =
                    make_float2(acc[nt][0] + sBq[col], acc[nt][1] + sBq[col + 1]);
                if (gr1 < N) *(float2*)(g_q + (size_t)gr1 * 128 + col) =
                    make_float2(acc[nt][2] + sBq[col], acc[nt][3] + sBq[col + 1]);
            }
        }
        // ---- v ----
        mma_tile(AH, AL, WvH, WvL, lane, wr, wc, acc);
        {
            int r = wr + (lane >> 2);
            int gr0 = row0 + r, gr1 = gr0 + 8;
#pragma unroll
            for (int nt = 0; nt < 8; nt++) {
                int col = wc + nt * 8 + qp;
                if (gr0 < N) *(float2*)(g_v + (size_t)gr0 * 128 + col) =
                    make_float2(acc[nt][0] + sBv[col], acc[nt][1] + sBv[col + 1]);
                if (gr1 < N) *(float2*)(g_v + (size_t)gr1 * 128 + col) =
                    make_float2(acc[nt][2] + sBv[col], acc[nt][3] + sBv[col + 1]);
            }
        }
        __syncthreads();   // A reads done before next conversion
    }
}

// persistent fused: k = edge_h@Wk^T+bk (HMMA, k-tile stays in smem)
//                   -> logits -> exp -> denominator atomics
__global__ void __launch_bounds__(512, 1) k_logits_tc_kernel(const float* __restrict__ edge_h,
        const float* __restrict__ Wk, const float* __restrict__ bk,
        const int* __restrict__ src, const int* __restrict__ dst, int E) {
    extern __shared__ char sm[];
    int tid = threadIdx.x, wid = tid >> 5, lane = tid & 31;
    __nv_bfloat16* WH = (__nv_bfloat16*)(sm + K_WH);
    __nv_bfloat16* WL = (__nv_bfloat16*)(sm + K_WL);
    __nv_bfloat16* AH = (__nv_bfloat16*)(sm + K_AH);
    __nv_bfloat16* AL = (__nv_bfloat16*)(sm + K_AL);
    float* kf = (float*)(sm + K_KF);
    float* sB = (float*)(sm + K_SB);
    load_conv<512, false>(Wk, 0, 128, WH, WL, tid, nullptr);
    if (tid < 128) sB[tid] = bk[tid];
    __syncthreads();
    int wr = (wid >> 1) << 4, wc = (wid & 1) << 6;
    int qp = (lane & 3) * 2;
    int et0 = tid >> 3, h = tid & 7;      // epilogue: edge-in-tile 0..63 (+64), head
    int ntiles = (E + 127) >> 7;
    for (int tile = blockIdx.x; tile < ntiles; tile += gridDim.x) {
        int row0 = tile << 7;
        load_conv<512, false>(edge_h, row0, E, AH, AL, tid, nullptr);
        // preload epilogue indices; latency hides under the GEMM
        int e0 = row0 + et0, e1 = e0 + 64;
        bool v0 = e0 < E, v1 = e1 < E;
        int s0 = 0, d0 = 0, s1 = 0, d1 = 0;
        if (v0) { s0 = __ldg(src + e0); d0 = __ldg(dst + e0); }
        if (v1) { s1 = __ldg(src + e1); d1 = __ldg(dst + e1); }
        __syncthreads();
        float acc[8][4];
        mma_tile(AH, AL, WH, WL, lane, wr, wc, acc);
        // write k tile (+bias) into smem
        {
            int r = wr + (lane >> 2);
#pragma unroll
            for (int nt = 0; nt < 8; nt++) {
                int col = wc + nt * 8 + qp;
                *(float2*)(kf + r * KPW + col) =
                    make_float2(acc[nt][0] + sB[col], acc[nt][1] + sB[col + 1]);
                *(float2*)(kf + (r + 8) * KPW + col) =
                    make_float2(acc[nt][2] + sB[col], acc[nt][3] + sB[col + 1]);
            }
        }
        __syncthreads();
        // ---- epilogue: 1024 (edge,head) items on 512 threads
        {
            float4 qs0[4], qd0[4], qs1[4], qd1[4];
            if (v0) {
                const float4* ps = (const float4*)(g_q + (size_t)s0 * 128 + h * 16);
                const float4* pd = (const float4*)(g_q + (size_t)d0 * 128 + h * 16);
#pragma unroll
                for (int j = 0; j < 4; j++) { qs0[j] = ps[j]; qd0[j] = pd[j]; }
            }
            if (v1) {
                const float4* ps = (const float4*)(g_q + (size_t)s1 * 128 + h * 16);
                const float4* pd = (const float4*)(g_q + (size_t)d1 * 128 + h * 16);
#pragma unroll
                for (int j = 0; j < 4; j++) { qs1[j] = ps[j]; qd1[j] = pd[j]; }
            }
            if (v0) {
                const float4* kk = (const float4*)(kf + et0 * KPW + h * 16);
                float im = 0.f, om = 0.f, dg = 0.f;
#pragma unroll
                for (int j = 0; j < 4; j++) {
                    float4 a = qs0[j], b = qd0[j], c = kk[j];
                    im += a.x*c.x + a.y*c.y + a.z*c.z + a.w*c.w;
                    om += b.x*c.x + b.y*c.y + b.z*c.z + b.w*c.w;
                    dg += a.x*b.x + a.y*b.y + a.z*b.z + a.w*b.w;
                }
                float ein = __expf(im * SCALE), eou = __expf(om * SCALE), edg = __expf(dg * SCALE);
                size_t o = (size_t)e0 * NHEADS + h;
                g_Ein[o] = ein; g_Eou[o] = eou; g_Edg[o] = edg;
                int idx = d0 * NHEADS + h;
                atomicAdd(&g_D[idx], ein);
                atomicAdd(&g_D[OFFM + idx], eou);
                atomicAdd(&g_D[2 * OFFM + idx], edg);
            }
            if (v1) {
                const float4* kk = (const float4*)(kf + (et0 + 64) * KPW + h * 16);
                float im = 0.f, om = 0.f, dg = 0.f;
#pragma unroll
                for (int j = 0; j < 4; j++) {
                    float4 a = qs1[j], b = qd1[j], c = kk[j];
                    im += a.x*c.x + a.y*c.y + a.z*c.z + a.w*c.w;
                    om += b.x*c.x + b.y*c.y + b.z*c.z + b.w*c.w;
                    dg += a.x*b.x + a.y*b.y + a.z*b.z + a.w*b.w;
                }
                float ein = __expf(im * SCALE), eou = __expf(om * SCALE), edg = __expf(dg * SCALE);
                size_t o = (size_t)e1 * NHEADS + h;
                g_Ein[o] = ein; g_Eou[o] = eou; g_Edg[o] = edg;
                int idx = d1 * NHEADS + h;
                atomicAdd(&g_D[idx], ein);
                atomicAdd(&g_D[OFFM + idx], eou);
                atomicAdd(&g_D[2 * OFFM + idx], edg);
            }
        }
        __syncthreads();   // epilogue kf reads done before next tile writes
    }
}

// persistent: out = leaky_relu( (S ⊙ v) @ Wo^T + bo )
__global__ void __launch_bounds__(512, 1) out_tc_kernel(const float* __restrict__ Wo,
        const float* __restrict__ bo, float* __restrict__ out, int N) {
    extern __shared__ char sm[];
    int tid = threadIdx.x, wid = tid >> 5, lane = tid & 31;
    __nv_bfloat16* WH = (__nv_bfloat16*)(sm + O_WH);
    __nv_bfloat16* WL = (__nv_bfloat16*)(sm + O_WL);
    __nv_bfloat16* AH = (__nv_bfloat16*)(sm + O_AH);
    __nv_bfloat16* AL = (__nv_bfloat16*)(sm + O_AL);
    float* sB = (float*)(sm + O_SB);
    load_conv<512, false>(Wo, 0, 128, WH, WL, tid, nullptr);
    if (tid < 128) sB[tid] = bo[tid];
    __syncthreads();
    int wr = (wid >> 1) << 4, wc = (wid & 1) << 6;
    int qp = (lane & 3) * 2;
    int ntiles = (N + 127) >> 7;
    for (int tile = blockIdx.x; tile < ntiles; tile += gridDim.x) {
        int row0 = tile << 7;
        load_conv<512, true>(g_v, row0, N, AH, AL, tid, g_S);
        __syncthreads();
        float acc[8][4];
        mma_tile(AH, AL, WH, WL, lane, wr, wc, acc);
        {
            int r = wr + (lane >> 2);
            int gr0 = row0 + r, gr1 = gr0 + 8;
#pragma unroll
            for (int nt = 0; nt < 8; nt++) {
                int col = wc + nt * 8 + qp;
                float x0 = acc[nt][0] + sB[col],   x1 = acc[nt][1] + sB[col + 1];
                float x2 = acc[nt][2] + sB[col],   x3 = acc[nt][3] + sB[col + 1];
                x0 = (x0 > 0.f) ? x0 : 0.1f * x0;  x1 = (x1 > 0.f) ? x1 : 0.1f * x1;
                x2 = (x2 > 0.f) ? x2 : 0.1f * x2;  x3 = (x3 > 0.f) ? x3 : 0.1f * x3;
                if (gr0 < N) *(float2*)(out + (size_t)gr0 * 128 + col) = make_float2(x0, x1);
                if (gr1 < N) *(float2*)(out + (size_t)gr1 * 128 + col) = make_float2(x2, x3);
            }
        }
        __syncthreads();
    }
}

__global__ void init_kernel(const float* __restrict__ dist,
                            const float* __restrict__ lam, int E) {
    int t = blockIdx.x * blockDim.x + threadIdx.x;
    if (t < 3 * OFFM) g_D[t] = 0.f;
    if (t < OFFM) g_S[t] = 0.f;
    if (t < E) g_att[t] = powf(dist[t], lam[0]);
}

__global__ void recip_kernel(int N) {
    int t = blockIdx.x * blockDim.x + threadIdx.x;
    if (t >= N * NHEADS) return;
#pragma unroll
    for (int k = 0; k < 3; k++) {
        float d = g_D[k * OFFM + t];
        g_Di[k * OFFM + t] = (d != 0.f) ? 1.f / d : 0.f;
    }
}

__global__ void score_kernel(const int* __restrict__ dst, int E) {
    int t = blockIdx.x * blockDim.x + threadIdx.x;
    if (t >= E * NHEADS) return;
    int e = t >> 3, h = t & 7;
    int idx = dst[e] * NHEADS + h;
    float s = g_Ein[t] * g_Di[idx]
            + g_Eou[t] * g_Di[OFFM + idx]
            + g_Edg[t] * g_Di[2 * OFFM + idx];
    atomicAdd(&g_S[idx], s * g_att[e]);
}

// ---------------- launch -----------------------------------------------------
extern "C" void kernel_launch(void* const* d_in, const int* in_sizes, int n_in,
                              void* d_out, int out_size) {
    const float* node_h   = (const float*)d_in[0];
    const float* edge_h   = (const float*)d_in[1];
    const float* distance = (const float*)d_in[2];
    const float* Wq = (const float*)d_in[3];  const float* bq = (const float*)d_in[4];
    const float* Wk = (const float*)d_in[5];  const float* bk = (const float*)d_in[6];
    const float* Wv = (const float*)d_in[7];  const float* bv = (const float*)d_in[8];
    const float* Wo = (const float*)d_in[9];  const float* bo = (const float*)d_in[10];
    const float* lam = (const float*)d_in[11];
    const int*   src = (const int*)d_in[12];
    const int*   dst = (const int*)d_in[13];

    int N = in_sizes[0] / F;
    int E = in_sizes[12];
    float* out = (float*)d_out;

    cudaFuncSetAttribute(qv_tc_kernel, cudaFuncAttributeMaxDynamicSharedMemorySize, QV_SMEM);
    cudaFuncSetAttribute(k_logits_tc_kernel, cudaFuncAttributeMaxDynamicSharedMemorySize, K_SMEM);
    cudaFuncSetAttribute(out_tc_kernel, cudaFuncAttributeMaxDynamicSharedMemorySize, O_SMEM);

    int ib = (3 * OFFM + 255) / 256;
    init_kernel<<<ib, 256>>>(distance, lam, E);

    qv_tc_kernel<<<PGRID, 512, QV_SMEM>>>(node_h, Wq, bq, Wv, bv, N);

    k_logits_tc_kernel<<<PGRID, 512, K_SMEM>>>(edge_h, Wk, bk, src, dst, E);

    int tb = (E * NHEADS + 255) / 256;
    int db = (N * NHEADS + 255) / 256;
    recip_kernel<<<db, 256>>>(N);
    score_kernel<<<tb, 256>>>(dst, E);

    out_tc_kernel<<<PGRID, 512, O_SMEM>>>(Wo, bo, out, N);
}